// round 4
// baseline (speedup 1.0000x reference)
#include <cuda_runtime.h>

// RotationPerturbationLayer as zero-padded bilinear rotation resample.
// theta: [B=4] degrees, image: [C=3, H=80, W=80] fp32 -> out [B, C, H, W].
//
// R2: latency-bound micro-opt. 3D launch eliminates integer div + tail guard;
// block=(80,4), grid=(20,B) = 80 blocks x 320 threads = exactly B*H*W threads,
// single wave, 10 warps per active SM for load-latency hiding.

#define H 80
#define W 80
#define C 3
#define B 4
#define NPIX (H * W)

__global__ __launch_bounds__(320)
void rot_bilinear_kernel(const float* __restrict__ theta,
                         const float* __restrict__ image,
                         float* __restrict__ out) {
    const int x = threadIdx.x;                       // 0..79
    const int y = blockIdx.x * 4 + threadIdx.y;      // 0..79
    const int b = blockIdx.y;                        // 0..3

    const float cx = (W - 1) * 0.5f;   // 39.5
    const float cy = (H - 1) * 0.5f;

    // deg -> rad; all threads in block share b (broadcast L2 load)
    float th = theta[b] * 0.017453292519943295f;
    float s, c;
    __sincosf(th, &s, &c);

    float x_rel = (float)x - cx;
    float y_rel = (float)y - cy;

    // rotation matrix [[cos, sin], [-sin, cos]]
    float src_x = fmaf(c,  x_rel, fmaf(s, y_rel, cx));
    float src_y = fmaf(-s, x_rel, fmaf(c, y_rel, cy));

    float fx0 = floorf(src_x);
    float fy0 = floorf(src_y);
    int x0 = (int)fx0;
    int y0 = (int)fy0;
    int x1 = x0 + 1;
    int y1 = y0 + 1;
    float ax = src_x - fx0;
    float ay = src_y - fy0;

    float w00 = (1.0f - ax) * (1.0f - ay);
    float w10 = ax * (1.0f - ay);
    float w01 = (1.0f - ax) * ay;
    float w11 = ax * ay;

    bool x0ok = (x0 >= 0) & (x0 < W);
    bool x1ok = (x1 >= 0) & (x1 < W);
    bool y0ok = (y0 >= 0) & (y0 < H);
    bool y1ok = (y1 >= 0) & (y1 < H);

    float m00 = (x0ok & y0ok) ? w00 : 0.0f;
    float m10 = (x1ok & y0ok) ? w10 : 0.0f;
    float m01 = (x0ok & y1ok) ? w01 : 0.0f;
    float m11 = (x1ok & y1ok) ? w11 : 0.0f;

    int xc0 = min(max(x0, 0), W - 1);
    int xc1 = min(max(x1, 0), W - 1);
    int yc0 = min(max(y0, 0), H - 1);
    int yc1 = min(max(y1, 0), H - 1);

    int i00 = yc0 * W + xc0;
    int i10 = yc0 * W + xc1;
    int i01 = yc1 * W + xc0;
    int i11 = yc1 * W + xc1;

    // Batch all 12 gathers (MLP=12) before consuming.
    float v00_0 = __ldg(image + 0 * NPIX + i00);
    float v10_0 = __ldg(image + 0 * NPIX + i10);
    float v01_0 = __ldg(image + 0 * NPIX + i01);
    float v11_0 = __ldg(image + 0 * NPIX + i11);
    float v00_1 = __ldg(image + 1 * NPIX + i00);
    float v10_1 = __ldg(image + 1 * NPIX + i10);
    float v01_1 = __ldg(image + 1 * NPIX + i01);
    float v11_1 = __ldg(image + 1 * NPIX + i11);
    float v00_2 = __ldg(image + 2 * NPIX + i00);
    float v10_2 = __ldg(image + 2 * NPIX + i10);
    float v01_2 = __ldg(image + 2 * NPIX + i01);
    float v11_2 = __ldg(image + 2 * NPIX + i11);

    int pix = y * W + x;
    float* ob = out + (size_t)b * C * NPIX + pix;

    float r0 = m00 * v00_0;
    r0 = fmaf(m10, v10_0, r0);
    r0 = fmaf(m01, v01_0, r0);
    r0 = fmaf(m11, v11_0, r0);

    float r1 = m00 * v00_1;
    r1 = fmaf(m10, v10_1, r1);
    r1 = fmaf(m01, v01_1, r1);
    r1 = fmaf(m11, v11_1, r1);

    float r2 = m00 * v00_2;
    r2 = fmaf(m10, v10_2, r2);
    r2 = fmaf(m01, v01_2, r2);
    r2 = fmaf(m11, v11_2, r2);

    ob[0 * NPIX] = r0;
    ob[1 * NPIX] = r1;
    ob[2 * NPIX] = r2;
}

extern "C" void kernel_launch(void* const* d_in, const int* in_sizes, int n_in,
                              void* d_out, int out_size) {
    const float* theta = (const float*)d_in[0];
    const float* image = (const float*)d_in[1];
    if (n_in >= 2 && in_sizes[0] != 4 && in_sizes[1] == 4) {
        theta = (const float*)d_in[1];
        image = (const float*)d_in[0];
    }
    float* out = (float*)d_out;

    dim3 block(80, 4, 1);        // 320 threads
    dim3 grid(H / 4, B, 1);      // 20 x 4 = 80 blocks, exactly one wave
    rot_bilinear_kernel<<<grid, block>>>(theta, image, out);
}